// round 1
// baseline (speedup 1.0000x reference)
#include <cuda_runtime.h>
#include <cstdint>

#define NN 50000
#define DD 256
#define EE 400000
#define LN_EPS 1e-5f

// ---------------- device scratch (no allocations allowed) ----------------
__device__ float d_Wsum[DD * DD];            // (W0+W1+W2)/3
__device__ float d_h[(size_t)NN * DD];       // feat @ Wsum   (51.2 MB)
__device__ int   d_deg[3 * NN];
__device__ int   d_off[3 * (NN + 1)];
__device__ int   d_cur[3 * NN];
__device__ int   d_ss[3 * EE];               // src ids sorted by dst, per relation

// ---------------- helpers ----------------
__device__ __forceinline__ uint32_t f2tf32(float x) {
    uint32_t r;
    asm("cvt.rna.tf32.f32 %0, %1;" : "=r"(r) : "f"(x));
    return r;
}

__device__ __forceinline__ void mma_tf32(float (&d)[4], const uint32_t (&a)[4],
                                         const uint32_t (&b)[2]) {
    asm volatile(
        "mma.sync.aligned.m16n8k8.row.col.f32.tf32.tf32.f32 "
        "{%0,%1,%2,%3}, {%4,%5,%6,%7}, {%8,%9}, {%0,%1,%2,%3};\n"
        : "+f"(d[0]), "+f"(d[1]), "+f"(d[2]), "+f"(d[3])
        : "r"(a[0]), "r"(a[1]), "r"(a[2]), "r"(a[3]), "r"(b[0]), "r"(b[1]));
}

__device__ __forceinline__ float warp_sum(float v) {
#pragma unroll
    for (int o = 16; o; o >>= 1) v += __shfl_xor_sync(0xFFFFFFFFu, v, o);
    return v;
}

// ---------------- kernel 1: Wsum + zero deg ----------------
__global__ void prep_kernel(const float* __restrict__ W0, const float* __restrict__ W1,
                            const float* __restrict__ W2) {
    int stride = gridDim.x * blockDim.x;
    for (int i = blockIdx.x * blockDim.x + threadIdx.x; i < 3 * NN; i += stride) {
        if (i < DD * DD) d_Wsum[i] = (W0[i] + W1[i] + W2[i]) * (1.0f / 3.0f);
        d_deg[i] = 0;
    }
}

// ---------------- kernel 2: GEMM h = feat @ Wsum (tf32 tensor cores) ------
// BM=128 BN=64 BK=32, 256 threads, 8 warps in 4x2, each warp 32x32.
__global__ __launch_bounds__(256) void gemm_kernel(const float* __restrict__ feat) {
    __shared__ uint32_t As[128 * 36];  // [m][k], stride 36 (conflict-free frag loads)
    __shared__ uint32_t Bs[32 * 72];   // [k][n], stride 72

    const int t    = threadIdx.x;
    const int lane = t & 31, wid = t >> 5;
    const int g    = lane >> 2, tig = lane & 3;
    const int wm   = wid & 3, wn = wid >> 2;

    const int rowBase = blockIdx.x * 128;
    const int colBase = blockIdx.y * 64;

    float acc[2][4][4];
#pragma unroll
    for (int mf = 0; mf < 2; mf++)
#pragma unroll
        for (int nf = 0; nf < 4; nf++)
#pragma unroll
            for (int k = 0; k < 4; k++) acc[mf][nf][k] = 0.0f;

    const int aRow0 = t >> 3, aCol4 = t & 7;      // A: 4 float4 / thread
    const int bRow0 = t >> 4, bCol4 = t & 15;     // B: 2 float4 / thread

    for (int kt = 0; kt < DD; kt += 32) {
        // load A tile 128x32
#pragma unroll
        for (int rr = 0; rr < 4; rr++) {
            int r = aRow0 + rr * 32;
            int gr = rowBase + r;
            float4 v = make_float4(0.f, 0.f, 0.f, 0.f);
            if (gr < NN)
                v = *reinterpret_cast<const float4*>(&feat[(size_t)gr * DD + kt + aCol4 * 4]);
            uint4 u;
            u.x = f2tf32(v.x); u.y = f2tf32(v.y); u.z = f2tf32(v.z); u.w = f2tf32(v.w);
            *reinterpret_cast<uint4*>(&As[r * 36 + aCol4 * 4]) = u;
        }
        // load B tile 32x64
#pragma unroll
        for (int rr = 0; rr < 2; rr++) {
            int r = bRow0 + rr * 16;
            float4 v = *reinterpret_cast<const float4*>(&d_Wsum[(kt + r) * DD + colBase + bCol4 * 4]);
            uint4 u;
            u.x = f2tf32(v.x); u.y = f2tf32(v.y); u.z = f2tf32(v.z); u.w = f2tf32(v.w);
            *reinterpret_cast<uint4*>(&Bs[r * 72 + bCol4 * 4]) = u;
        }
        __syncthreads();

#pragma unroll
        for (int kk = 0; kk < 4; kk++) {
            uint32_t af[2][4], bf[4][2];
#pragma unroll
            for (int mf = 0; mf < 2; mf++) {
                int m0 = wm * 32 + mf * 16 + g;
                af[mf][0] = As[(m0)     * 36 + kk * 8 + tig];
                af[mf][1] = As[(m0 + 8) * 36 + kk * 8 + tig];
                af[mf][2] = As[(m0)     * 36 + kk * 8 + tig + 4];
                af[mf][3] = As[(m0 + 8) * 36 + kk * 8 + tig + 4];
            }
#pragma unroll
            for (int nf = 0; nf < 4; nf++) {
                int n0 = wn * 32 + nf * 8 + g;
                bf[nf][0] = Bs[(kk * 8 + tig)     * 72 + n0];
                bf[nf][1] = Bs[(kk * 8 + tig + 4) * 72 + n0];
            }
#pragma unroll
            for (int mf = 0; mf < 2; mf++)
#pragma unroll
                for (int nf = 0; nf < 4; nf++) mma_tf32(acc[mf][nf], af[mf], bf[nf]);
        }
        __syncthreads();
    }

    // epilogue
#pragma unroll
    for (int mf = 0; mf < 2; mf++)
#pragma unroll
        for (int nf = 0; nf < 4; nf++) {
            int r0 = rowBase + wm * 32 + mf * 16 + g;
            int c  = colBase + wn * 32 + nf * 8 + tig * 2;
            if (r0 < NN)
                *reinterpret_cast<float2*>(&d_h[(size_t)r0 * DD + c]) =
                    make_float2(acc[mf][nf][0], acc[mf][nf][1]);
            int r1 = r0 + 8;
            if (r1 < NN)
                *reinterpret_cast<float2*>(&d_h[(size_t)r1 * DD + c]) =
                    make_float2(acc[mf][nf][2], acc[mf][nf][3]);
        }
}

// ---------------- kernel 3: degree histogram ----------------
__global__ void hist_kernel(const int* __restrict__ dst0, const int* __restrict__ dst1,
                            const int* __restrict__ dst2) {
    int e = blockIdx.x * blockDim.x + threadIdx.x;
    int r = blockIdx.y;
    if (e >= EE) return;
    const int* dst = (r == 0) ? dst0 : (r == 1) ? dst1 : dst2;
    atomicAdd(&d_deg[r * NN + dst[e]], 1);
}

// ---------------- kernel 4: exclusive scan (one block per relation) ------
__global__ void scan_kernel() {
    int r = blockIdx.x;
    const int* dg = d_deg + r * NN;
    int* o = d_off + r * (NN + 1);
    int* c = d_cur + r * NN;

    __shared__ int warp_sums[32];
    __shared__ int s_carry;
    int tid = threadIdx.x;
    int lane = tid & 31, wid = tid >> 5;
    if (tid == 0) s_carry = 0;
    __syncthreads();

    for (int base = 0; base < NN; base += 1024) {
        int i = base + tid;
        int v = (i < NN) ? dg[i] : 0;
        int x = v;
#pragma unroll
        for (int ofs = 1; ofs < 32; ofs <<= 1) {
            int y = __shfl_up_sync(0xFFFFFFFFu, x, ofs);
            if (lane >= ofs) x += y;
        }
        if (lane == 31) warp_sums[wid] = x;
        __syncthreads();
        if (wid == 0) {
            int w = warp_sums[lane];
#pragma unroll
            for (int ofs = 1; ofs < 32; ofs <<= 1) {
                int y = __shfl_up_sync(0xFFFFFFFFu, w, ofs);
                if (lane >= ofs) w += y;
            }
            warp_sums[lane] = w;
        }
        __syncthreads();
        int block_excl = (wid > 0) ? warp_sums[wid - 1] : 0;
        int excl = x - v + block_excl + s_carry;
        if (i < NN) { o[i] = excl; c[i] = excl; }
        int total = warp_sums[31];
        __syncthreads();
        if (tid == 0) s_carry += total;
        __syncthreads();
    }
    if (tid == 0) o[NN] = s_carry;
}

// ---------------- kernel 5: scatter into CSR ----------------
__global__ void scatter_kernel(const int* __restrict__ src0, const int* __restrict__ dst0,
                               const int* __restrict__ src1, const int* __restrict__ dst1,
                               const int* __restrict__ src2, const int* __restrict__ dst2) {
    int e = blockIdx.x * blockDim.x + threadIdx.x;
    int r = blockIdx.y;
    if (e >= EE) return;
    const int* src = (r == 0) ? src0 : (r == 1) ? src1 : src2;
    const int* dst = (r == 0) ? dst0 : (r == 1) ? dst1 : dst2;
    int dv = dst[e];
    int pos = atomicAdd(&d_cur[r * NN + dv], 1);
    d_ss[r * EE + pos] = src[e];
}

// ---------------- kernel 6: gather + mean + relu + LN (warp per node) ----
__global__ __launch_bounds__(256) void agg_ln_kernel(const float* __restrict__ gamma,
                                                     const float* __restrict__ beta,
                                                     float* __restrict__ out) {
    int v = (blockIdx.x * blockDim.x + threadIdx.x) >> 5;
    if (v >= NN) return;
    int lane = threadIdx.x & 31;

    float acc[8];
#pragma unroll
    for (int j = 0; j < 8; j++) acc[j] = 0.0f;

#pragma unroll
    for (int r = 0; r < 3; r++) {
        int s = d_off[r * (NN + 1) + v];
        int e = d_off[r * (NN + 1) + v + 1];
        float sm[8];
#pragma unroll
        for (int j = 0; j < 8; j++) sm[j] = 0.0f;
        for (int i = s; i < e; i++) {
            int u = d_ss[r * EE + i];
            const float4* row = reinterpret_cast<const float4*>(&d_h[(size_t)u * DD]);
            float4 p = row[lane];
            float4 q = row[lane + 32];
            sm[0] += p.x; sm[1] += p.y; sm[2] += p.z; sm[3] += p.w;
            sm[4] += q.x; sm[5] += q.y; sm[6] += q.z; sm[7] += q.w;
        }
        float inv = 1.0f / (float)max(e - s, 1);
#pragma unroll
        for (int j = 0; j < 8; j++) acc[j] += sm[j] * inv;
    }

#pragma unroll
    for (int j = 0; j < 8; j++) acc[j] = fmaxf(acc[j] * (1.0f / 3.0f), 0.0f);

    float loc = 0.0f;
#pragma unroll
    for (int j = 0; j < 8; j++) loc += acc[j];
    float mu = warp_sum(loc) * (1.0f / 256.0f);

    float vs = 0.0f;
#pragma unroll
    for (int j = 0; j < 8; j++) {
        float dlt = acc[j] - mu;
        vs += dlt * dlt;
    }
    float var = warp_sum(vs) * (1.0f / 256.0f);
    float rstd = rsqrtf(var + LN_EPS);

    const float4* g4 = reinterpret_cast<const float4*>(gamma);
    const float4* b4 = reinterpret_cast<const float4*>(beta);
    float4 ga = g4[lane], gb = g4[lane + 32];
    float4 ba = b4[lane], bb = b4[lane + 32];

    float4 o0, o1;
    o0.x = (acc[0] - mu) * rstd * ga.x + ba.x;
    o0.y = (acc[1] - mu) * rstd * ga.y + ba.y;
    o0.z = (acc[2] - mu) * rstd * ga.z + ba.z;
    o0.w = (acc[3] - mu) * rstd * ga.w + ba.w;
    o1.x = (acc[4] - mu) * rstd * gb.x + bb.x;
    o1.y = (acc[5] - mu) * rstd * gb.y + bb.y;
    o1.z = (acc[6] - mu) * rstd * gb.z + bb.z;
    o1.w = (acc[7] - mu) * rstd * gb.w + bb.w;

    float4* out4 = reinterpret_cast<float4*>(&out[(size_t)v * DD]);
    out4[lane] = o0;
    out4[lane + 32] = o1;
}

// ---------------- launch ----------------
extern "C" void kernel_launch(void* const* d_in, const int* in_sizes, int n_in,
                              void* d_out, int out_size) {
    const float* feat  = (const float*)d_in[0];
    const float* W0    = (const float*)d_in[1];
    const float* W1    = (const float*)d_in[2];
    const float* W2    = (const float*)d_in[3];
    const float* gamma = (const float*)d_in[7];
    const float* beta  = (const float*)d_in[8];
    const int* src0 = (const int*)d_in[9];
    const int* dst0 = (const int*)d_in[10];
    const int* src1 = (const int*)d_in[11];
    const int* dst1 = (const int*)d_in[12];
    const int* src2 = (const int*)d_in[13];
    const int* dst2 = (const int*)d_in[14];
    float* out = (float*)d_out;

    prep_kernel<<<256, 256>>>(W0, W1, W2);

    dim3 ggrid((NN + 127) / 128, DD / 64);
    gemm_kernel<<<ggrid, 256>>>(feat);

    dim3 egrid((EE + 255) / 256, 3);
    hist_kernel<<<egrid, 256>>>(dst0, dst1, dst2);
    scan_kernel<<<3, 1024>>>();
    scatter_kernel<<<egrid, 256>>>(src0, dst0, src1, dst1, src2, dst2);

    agg_ln_kernel<<<(NN * 32 + 255) / 256, 256>>>(gamma, beta, out);
}

// round 2
// speedup vs baseline: 1.3068x; 1.3068x over previous
#include <cuda_runtime.h>
#include <cuda_fp16.h>
#include <cstdint>

#define NN 50000
#define DD 256
#define EE 400000
#define LN_EPS 1e-5f

#define M_TOT (3 * NN)              // 150000 degree counters, globally scanned
#define NB ((M_TOT + 1023) / 1024)  // 147 scan blocks

// ---------------- device scratch (no allocations allowed) ----------------
__device__ float  d_Wsum[DD * DD];            // (W0+W1+W2)/3
__device__ __half d_h[(size_t)NN * DD];       // feat @ Wsum   (25.6 MB, fp16)
__device__ int    d_deg[M_TOT];
__device__ int    d_off[M_TOT + 1];           // global exclusive scan of deg
__device__ int    d_cur[M_TOT];
__device__ int    d_ss[3 * EE];               // src ids grouped by (rel, dst)
__device__ int    d_bsum[NB];

// ---------------- helpers ----------------
__device__ __forceinline__ uint32_t f2tf32(float x) {
    uint32_t r;
    asm("cvt.rna.tf32.f32 %0, %1;" : "=r"(r) : "f"(x));
    return r;
}

__device__ __forceinline__ void mma_tf32(float (&d)[4], const uint32_t (&a)[4],
                                         const uint32_t (&b)[2]) {
    asm volatile(
        "mma.sync.aligned.m16n8k8.row.col.f32.tf32.tf32.f32 "
        "{%0,%1,%2,%3}, {%4,%5,%6,%7}, {%8,%9}, {%0,%1,%2,%3};\n"
        : "+f"(d[0]), "+f"(d[1]), "+f"(d[2]), "+f"(d[3])
        : "r"(a[0]), "r"(a[1]), "r"(a[2]), "r"(a[3]), "r"(b[0]), "r"(b[1]));
}

__device__ __forceinline__ float warp_sum(float v) {
#pragma unroll
    for (int o = 16; o; o >>= 1) v += __shfl_xor_sync(0xFFFFFFFFu, v, o);
    return v;
}

__device__ __forceinline__ int warp_iscan(int x, int lane) {
#pragma unroll
    for (int ofs = 1; ofs < 32; ofs <<= 1) {
        int y = __shfl_up_sync(0xFFFFFFFFu, x, ofs);
        if (lane >= ofs) x += y;
    }
    return x;
}

// ---------------- kernel 1: Wsum + zero deg ----------------
__global__ void prep_kernel(const float* __restrict__ W0, const float* __restrict__ W1,
                            const float* __restrict__ W2) {
    int stride = gridDim.x * blockDim.x;
    for (int i = blockIdx.x * blockDim.x + threadIdx.x; i < M_TOT; i += stride) {
        if (i < DD * DD) d_Wsum[i] = (W0[i] + W1[i] + W2[i]) * (1.0f / 3.0f);
        d_deg[i] = 0;
    }
}

// ---------------- kernel 2: GEMM h = feat @ Wsum (tf32 tensor cores) ------
__global__ __launch_bounds__(256) void gemm_kernel(const float* __restrict__ feat) {
    __shared__ uint32_t As[128 * 36];
    __shared__ uint32_t Bs[32 * 72];

    const int t    = threadIdx.x;
    const int lane = t & 31, wid = t >> 5;
    const int g    = lane >> 2, tig = lane & 3;
    const int wm   = wid & 3, wn = wid >> 2;

    const int rowBase = blockIdx.x * 128;
    const int colBase = blockIdx.y * 64;

    float acc[2][4][4];
#pragma unroll
    for (int mf = 0; mf < 2; mf++)
#pragma unroll
        for (int nf = 0; nf < 4; nf++)
#pragma unroll
            for (int k = 0; k < 4; k++) acc[mf][nf][k] = 0.0f;

    const int aRow0 = t >> 3, aCol4 = t & 7;
    const int bRow0 = t >> 4, bCol4 = t & 15;

    for (int kt = 0; kt < DD; kt += 32) {
#pragma unroll
        for (int rr = 0; rr < 4; rr++) {
            int r = aRow0 + rr * 32;
            int gr = rowBase + r;
            float4 v = make_float4(0.f, 0.f, 0.f, 0.f);
            if (gr < NN)
                v = *reinterpret_cast<const float4*>(&feat[(size_t)gr * DD + kt + aCol4 * 4]);
            uint4 u;
            u.x = f2tf32(v.x); u.y = f2tf32(v.y); u.z = f2tf32(v.z); u.w = f2tf32(v.w);
            *reinterpret_cast<uint4*>(&As[r * 36 + aCol4 * 4]) = u;
        }
#pragma unroll
        for (int rr = 0; rr < 2; rr++) {
            int r = bRow0 + rr * 16;
            float4 v = *reinterpret_cast<const float4*>(&d_Wsum[(kt + r) * DD + colBase + bCol4 * 4]);
            uint4 u;
            u.x = f2tf32(v.x); u.y = f2tf32(v.y); u.z = f2tf32(v.z); u.w = f2tf32(v.w);
            *reinterpret_cast<uint4*>(&Bs[r * 72 + bCol4 * 4]) = u;
        }
        __syncthreads();

#pragma unroll
        for (int kk = 0; kk < 4; kk++) {
            uint32_t af[2][4], bf[4][2];
#pragma unroll
            for (int mf = 0; mf < 2; mf++) {
                int m0 = wm * 32 + mf * 16 + g;
                af[mf][0] = As[(m0)     * 36 + kk * 8 + tig];
                af[mf][1] = As[(m0 + 8) * 36 + kk * 8 + tig];
                af[mf][2] = As[(m0)     * 36 + kk * 8 + tig + 4];
                af[mf][3] = As[(m0 + 8) * 36 + kk * 8 + tig + 4];
            }
#pragma unroll
            for (int nf = 0; nf < 4; nf++) {
                int n0 = wn * 32 + nf * 8 + g;
                bf[nf][0] = Bs[(kk * 8 + tig)     * 72 + n0];
                bf[nf][1] = Bs[(kk * 8 + tig + 4) * 72 + n0];
            }
#pragma unroll
            for (int mf = 0; mf < 2; mf++)
#pragma unroll
                for (int nf = 0; nf < 4; nf++) mma_tf32(acc[mf][nf], af[mf], bf[nf]);
        }
        __syncthreads();
    }

    // epilogue -> fp16
#pragma unroll
    for (int mf = 0; mf < 2; mf++)
#pragma unroll
        for (int nf = 0; nf < 4; nf++) {
            int r0 = rowBase + wm * 32 + mf * 16 + g;
            int c  = colBase + wn * 32 + nf * 8 + tig * 2;
            if (r0 < NN)
                *reinterpret_cast<__half2*>(&d_h[(size_t)r0 * DD + c]) =
                    __floats2half2_rn(acc[mf][nf][0], acc[mf][nf][1]);
            int r1 = r0 + 8;
            if (r1 < NN)
                *reinterpret_cast<__half2*>(&d_h[(size_t)r1 * DD + c]) =
                    __floats2half2_rn(acc[mf][nf][2], acc[mf][nf][3]);
        }
}

// ---------------- kernel 3: degree histogram ----------------
__global__ void hist_kernel(const int* __restrict__ dst0, const int* __restrict__ dst1,
                            const int* __restrict__ dst2) {
    int e = blockIdx.x * blockDim.x + threadIdx.x;
    int r = blockIdx.y;
    if (e >= EE) return;
    const int* dst = (r == 0) ? dst0 : (r == 1) ? dst1 : dst2;
    atomicAdd(&d_deg[r * NN + dst[e]], 1);
}

// ---------------- kernel 4a: per-block partial sums ----------------
__global__ __launch_bounds__(256) void scan_p1() {
    int b = blockIdx.x, t = threadIdx.x;
    int lane = t & 31, w = t >> 5;
    int base = b * 1024 + t * 4;
    int s = 0;
#pragma unroll
    for (int j = 0; j < 4; j++) {
        int i = base + j;
        if (i < M_TOT) s += d_deg[i];
    }
    s = warp_sum((float)s);  // reuse float warp_sum? no — do int
    // (int warp reduction)
    __shared__ int ws[8];
    // recompute properly with int shuffles:
    int x = 0;
#pragma unroll
    for (int j = 0; j < 4; j++) {
        int i = base + j;
        if (i < M_TOT) x += d_deg[i];
    }
#pragma unroll
    for (int o = 16; o; o >>= 1) x += __shfl_xor_sync(0xFFFFFFFFu, x, o);
    if (lane == 0) ws[w] = x;
    __syncthreads();
    if (t == 0) {
        int tot = 0;
#pragma unroll
        for (int j = 0; j < 8; j++) tot += ws[j];
        d_bsum[b] = tot;
    }
}

// ---------------- kernel 4b: scan the 147 block sums ----------------
__global__ __launch_bounds__(256) void scan_p2() {
    int t = threadIdx.x, lane = t & 31, w = t >> 5;
    int v = (t < NB) ? d_bsum[t] : 0;
    int x = warp_iscan(v, lane);
    __shared__ int ws[8];
    if (lane == 31) ws[w] = x;
    __syncthreads();
    if (w == 0) {
        int y = (lane < 8) ? ws[lane] : 0;
        y = warp_iscan(y, lane);
        if (lane < 8) ws[lane] = y;
    }
    __syncthreads();
    int blk = (w > 0) ? ws[w - 1] : 0;
    if (t < NB) d_bsum[t] = x - v + blk;   // exclusive
}

// ---------------- kernel 4c: final scan + write offsets ----------------
__global__ __launch_bounds__(256) void scan_p3() {
    int b = blockIdx.x, t = threadIdx.x;
    int lane = t & 31, w = t >> 5;
    int base = b * 1024 + t * 4;
    int a[4];
#pragma unroll
    for (int j = 0; j < 4; j++) {
        int i = base + j;
        a[j] = (i < M_TOT) ? d_deg[i] : 0;
    }
    int tot = a[0] + a[1] + a[2] + a[3];
    int x = warp_iscan(tot, lane);
    __shared__ int ws[8];
    if (lane == 31) ws[w] = x;
    __syncthreads();
    if (w == 0) {
        int y = (lane < 8) ? ws[lane] : 0;
        y = warp_iscan(y, lane);
        if (lane < 8) ws[lane] = y;
    }
    __syncthreads();
    int blk = (w > 0) ? ws[w - 1] : 0;
    int excl = x - tot + blk + d_bsum[b];
    int run = excl;
#pragma unroll
    for (int j = 0; j < 4; j++) {
        int i = base + j;
        if (i < M_TOT) { d_off[i] = run; d_cur[i] = run; }
        run += a[j];
    }
    if (b == 0 && t == 0) d_off[M_TOT] = 3 * EE;
}

// ---------------- kernel 5: scatter into CSR (global positions) ----------
__global__ void scatter_kernel(const int* __restrict__ src0, const int* __restrict__ dst0,
                               const int* __restrict__ src1, const int* __restrict__ dst1,
                               const int* __restrict__ src2, const int* __restrict__ dst2) {
    int e = blockIdx.x * blockDim.x + threadIdx.x;
    int r = blockIdx.y;
    if (e >= EE) return;
    const int* src = (r == 0) ? src0 : (r == 1) ? src1 : src2;
    const int* dst = (r == 0) ? dst0 : (r == 1) ? dst1 : dst2;
    int dv = dst[e];
    int pos = atomicAdd(&d_cur[r * NN + dv], 1);
    d_ss[pos] = src[e];
}

// ---------------- kernel 6: gather + mean + relu + LN (warp per node) ----
__global__ __launch_bounds__(256) void agg_ln_kernel(const float* __restrict__ gamma,
                                                     const float* __restrict__ beta,
                                                     float* __restrict__ out) {
    int v = (blockIdx.x * blockDim.x + threadIdx.x) >> 5;
    if (v >= NN) return;
    int lane = threadIdx.x & 31;

    float acc[8];
#pragma unroll
    for (int j = 0; j < 8; j++) acc[j] = 0.0f;

#pragma unroll
    for (int r = 0; r < 3; r++) {
        int s = d_off[r * NN + v];
        int e = d_off[r * NN + v + 1];
        float sm[8];
#pragma unroll
        for (int j = 0; j < 8; j++) sm[j] = 0.0f;
        for (int i = s; i < e; i++) {
            int u = d_ss[i];
            const uint2* row = reinterpret_cast<const uint2*>(&d_h[(size_t)u * DD]);
            uint2 p = row[lane];        // halves [lane*4,   +4)
            uint2 q = row[lane + 32];   // halves [128+lane*4, +4)
            float2 f0 = __half22float2(*reinterpret_cast<__half2*>(&p.x));
            float2 f1 = __half22float2(*reinterpret_cast<__half2*>(&p.y));
            float2 f2 = __half22float2(*reinterpret_cast<__half2*>(&q.x));
            float2 f3 = __half22float2(*reinterpret_cast<__half2*>(&q.y));
            sm[0] += f0.x; sm[1] += f0.y; sm[2] += f1.x; sm[3] += f1.y;
            sm[4] += f2.x; sm[5] += f2.y; sm[6] += f3.x; sm[7] += f3.y;
        }
        float inv = 1.0f / (float)max(e - s, 1);
#pragma unroll
        for (int j = 0; j < 8; j++) acc[j] += sm[j] * inv;
    }

#pragma unroll
    for (int j = 0; j < 8; j++) acc[j] = fmaxf(acc[j] * (1.0f / 3.0f), 0.0f);

    float loc = 0.0f;
#pragma unroll
    for (int j = 0; j < 8; j++) loc += acc[j];
    float mu = warp_sum(loc) * (1.0f / 256.0f);

    float vs = 0.0f;
#pragma unroll
    for (int j = 0; j < 8; j++) {
        float dlt = acc[j] - mu;
        vs += dlt * dlt;
    }
    float var = warp_sum(vs) * (1.0f / 256.0f);
    float rstd = rsqrtf(var + LN_EPS);

    const float4* g4 = reinterpret_cast<const float4*>(gamma);
    const float4* b4 = reinterpret_cast<const float4*>(beta);
    float4 ga = g4[lane], gb = g4[lane + 32];
    float4 ba = b4[lane], bb = b4[lane + 32];

    float4 o0, o1;
    o0.x = (acc[0] - mu) * rstd * ga.x + ba.x;
    o0.y = (acc[1] - mu) * rstd * ga.y + ba.y;
    o0.z = (acc[2] - mu) * rstd * ga.z + ba.z;
    o0.w = (acc[3] - mu) * rstd * ga.w + ba.w;
    o1.x = (acc[4] - mu) * rstd * gb.x + bb.x;
    o1.y = (acc[5] - mu) * rstd * gb.y + bb.y;
    o1.z = (acc[6] - mu) * rstd * gb.z + bb.z;
    o1.w = (acc[7] - mu) * rstd * gb.w + bb.w;

    float4* out4 = reinterpret_cast<float4*>(&out[(size_t)v * DD]);
    out4[lane] = o0;
    out4[lane + 32] = o1;
}

// ---------------- launch ----------------
extern "C" void kernel_launch(void* const* d_in, const int* in_sizes, int n_in,
                              void* d_out, int out_size) {
    const float* feat  = (const float*)d_in[0];
    const float* W0    = (const float*)d_in[1];
    const float* W1    = (const float*)d_in[2];
    const float* W2    = (const float*)d_in[3];
    const float* gamma = (const float*)d_in[7];
    const float* beta  = (const float*)d_in[8];
    const int* src0 = (const int*)d_in[9];
    const int* dst0 = (const int*)d_in[10];
    const int* src1 = (const int*)d_in[11];
    const int* dst1 = (const int*)d_in[12];
    const int* src2 = (const int*)d_in[13];
    const int* dst2 = (const int*)d_in[14];
    float* out = (float*)d_out;

    prep_kernel<<<256, 256>>>(W0, W1, W2);

    dim3 ggrid((NN + 127) / 128, DD / 64);
    gemm_kernel<<<ggrid, 256>>>(feat);

    dim3 egrid((EE + 255) / 256, 3);
    hist_kernel<<<egrid, 256>>>(dst0, dst1, dst2);
    scan_p1<<<NB, 256>>>();
    scan_p2<<<1, 256>>>();
    scan_p3<<<NB, 256>>>();
    scatter_kernel<<<egrid, 256>>>(src0, dst0, src1, dst1, src2, dst2);

    agg_ln_kernel<<<(NN * 32 + 255) / 256, 256>>>(gamma, beta, out);
}

// round 4
// speedup vs baseline: 1.4460x; 1.1065x over previous
#include <cuda_runtime.h>
#include <cuda_fp16.h>
#include <cstdint>

#define NN 50000
#define DD 256
#define EE 400000
#define LN_EPS 1e-5f

#define M_TOT (3 * NN)              // 150000 degree counters, globally scanned
#define NB ((M_TOT + 1023) / 1024)  // 147 scan blocks

// ---------------- device scratch (no allocations allowed) ----------------
__device__ __half d_Wh[DD * DD];              // ((W0+W1+W2)/3)^T in fp16, [n][k]
__device__ __half d_h[(size_t)NN * DD];       // feat @ Wsum   (25.6 MB, fp16)
__device__ int    d_deg[M_TOT];
__device__ int    d_off[M_TOT + 1];
__device__ int    d_cur[M_TOT];
__device__ int    d_ss[3 * EE];
__device__ int    d_bsum[NB];

// ---------------- helpers ----------------
__device__ __forceinline__ void mma_f16(float (&d)[4], const uint32_t (&a)[4],
                                        const uint32_t (&b)[2]) {
    asm volatile(
        "mma.sync.aligned.m16n8k16.row.col.f32.f16.f16.f32 "
        "{%0,%1,%2,%3}, {%4,%5,%6,%7}, {%8,%9}, {%0,%1,%2,%3};\n"
        : "+f"(d[0]), "+f"(d[1]), "+f"(d[2]), "+f"(d[3])
        : "r"(a[0]), "r"(a[1]), "r"(a[2]), "r"(a[3]), "r"(b[0]), "r"(b[1]));
}

__device__ __forceinline__ float warp_sum(float v) {
#pragma unroll
    for (int o = 16; o; o >>= 1) v += __shfl_xor_sync(0xFFFFFFFFu, v, o);
    return v;
}

__device__ __forceinline__ int warp_isum(int v) {
#pragma unroll
    for (int o = 16; o; o >>= 1) v += __shfl_xor_sync(0xFFFFFFFFu, v, o);
    return v;
}

__device__ __forceinline__ int warp_iscan(int x, int lane) {
#pragma unroll
    for (int ofs = 1; ofs < 32; ofs <<= 1) {
        int y = __shfl_up_sync(0xFFFFFFFFu, x, ofs);
        if (lane >= ofs) x += y;
    }
    return x;
}

// ---------------- kernel 1: Wsum^T (fp16) + zero deg ----------------
__global__ void prep_kernel(const float* __restrict__ W0, const float* __restrict__ W1,
                            const float* __restrict__ W2) {
    int stride = gridDim.x * blockDim.x;
    for (int i = blockIdx.x * blockDim.x + threadIdx.x; i < M_TOT; i += stride) {
        if (i < DD * DD) {
            int n = i >> 8, k = i & 255;         // output [n][k]
            int src = k * DD + n;                 // input  [k][n]
            float w = (W0[src] + W1[src] + W2[src]) * (1.0f / 3.0f);
            d_Wh[i] = __float2half_rn(w);
        }
        d_deg[i] = 0;
    }
}

// ---------------- kernel 2: GEMM h = feat @ Wsum (fp16 mma, fp32 accum) ---
// BM=128 BN=64 BK=32, 256 threads, 8 warps (4 m x 2 n), warp tile 32x32.
__global__ __launch_bounds__(256) void gemm_kernel(const float* __restrict__ feat) {
    __shared__ uint32_t As[128 * 20];  // [m][k/2] half2-as-uint, stride 20
    __shared__ uint32_t Bs[64 * 20];   // [n][k/2]

    const int t    = threadIdx.x;
    const int lane = t & 31, wid = t >> 5;
    const int g    = lane >> 2, tig = lane & 3;
    const int wm   = wid & 3, wn = wid >> 2;

    const int rowBase = blockIdx.x * 128;
    const int colBase = blockIdx.y * 64;

    float acc[2][4][4];
#pragma unroll
    for (int mf = 0; mf < 2; mf++)
#pragma unroll
        for (int nf = 0; nf < 4; nf++)
#pragma unroll
            for (int k = 0; k < 4; k++) acc[mf][nf][k] = 0.0f;

    // A loader: 2 threads per row, 4 float4 each (row = t>>1, cols part*16..+15)
    const int aRow = t >> 1, aPart = t & 1;
    const int aGr  = rowBase + aRow;
    // B loader: 4 threads per row, 1 uint4 (8 halves) each
    const int bRow = t >> 2, bQ = t & 3;

    float4 aReg[4];
    uint4  bReg;

    auto loadTile = [&](int kt) {
#pragma unroll
        for (int j = 0; j < 4; j++) {
            aReg[j] = make_float4(0.f, 0.f, 0.f, 0.f);
            if (aGr < NN)
                aReg[j] = *reinterpret_cast<const float4*>(
                    &feat[(size_t)aGr * DD + kt + (aPart * 4 + j) * 4]);
        }
        bReg = *reinterpret_cast<const uint4*>(&d_Wh[(colBase + bRow) * DD + kt + bQ * 8]);
    };
    auto storeTile = [&]() {
#pragma unroll
        for (int j = 0; j < 4; j++) {
            __half2 lo = __floats2half2_rn(aReg[j].x, aReg[j].y);
            __half2 hi = __floats2half2_rn(aReg[j].z, aReg[j].w);
            uint2 u;
            u.x = *reinterpret_cast<uint32_t*>(&lo);
            u.y = *reinterpret_cast<uint32_t*>(&hi);
            *reinterpret_cast<uint2*>(&As[aRow * 20 + (aPart * 4 + j) * 2]) = u;
        }
        *reinterpret_cast<uint4*>(&Bs[bRow * 20 + bQ * 4]) = bReg;
    };

    loadTile(0);
    storeTile();
    __syncthreads();

#pragma unroll
    for (int kt = 0; kt < 8; kt++) {
        const bool more = (kt + 1) < 8;
        if (more) loadTile((kt + 1) * 32);

#pragma unroll
        for (int kk = 0; kk < 2; kk++) {
            uint32_t af[2][4], bf[4][2];
#pragma unroll
            for (int mf = 0; mf < 2; mf++) {
                int m0 = wm * 32 + mf * 16 + g;
                af[mf][0] = As[(m0)     * 20 + kk * 8 + tig];
                af[mf][1] = As[(m0 + 8) * 20 + kk * 8 + tig];
                af[mf][2] = As[(m0)     * 20 + kk * 8 + tig + 4];
                af[mf][3] = As[(m0 + 8) * 20 + kk * 8 + tig + 4];
            }
#pragma unroll
            for (int nf = 0; nf < 4; nf++) {
                int n0 = wn * 32 + nf * 8 + g;
                bf[nf][0] = Bs[n0 * 20 + kk * 8 + tig];
                bf[nf][1] = Bs[n0 * 20 + kk * 8 + tig + 4];
            }
#pragma unroll
            for (int mf = 0; mf < 2; mf++)
#pragma unroll
                for (int nf = 0; nf < 4; nf++) mma_f16(acc[mf][nf], af[mf], bf[nf]);
        }
        __syncthreads();
        if (more) {
            storeTile();
            __syncthreads();
        }
    }

    // epilogue -> fp16
#pragma unroll
    for (int mf = 0; mf < 2; mf++)
#pragma unroll
        for (int nf = 0; nf < 4; nf++) {
            int r0 = rowBase + wm * 32 + mf * 16 + g;
            int c  = colBase + wn * 32 + nf * 8 + tig * 2;
            if (r0 < NN)
                *reinterpret_cast<__half2*>(&d_h[(size_t)r0 * DD + c]) =
                    __floats2half2_rn(acc[mf][nf][0], acc[mf][nf][1]);
            int r1 = r0 + 8;
            if (r1 < NN)
                *reinterpret_cast<__half2*>(&d_h[(size_t)r1 * DD + c]) =
                    __floats2half2_rn(acc[mf][nf][2], acc[mf][nf][3]);
        }
}

// ---------------- kernel 3: degree histogram ----------------
__global__ void hist_kernel(const int* __restrict__ dst0, const int* __restrict__ dst1,
                            const int* __restrict__ dst2) {
    int e = blockIdx.x * blockDim.x + threadIdx.x;
    int r = blockIdx.y;
    if (e >= EE) return;
    const int* dst = (r == 0) ? dst0 : (r == 1) ? dst1 : dst2;
    atomicAdd(&d_deg[r * NN + dst[e]], 1);
}

// ---------------- kernel 4a: per-block partial sums ----------------
__global__ __launch_bounds__(256) void scan_p1() {
    int b = blockIdx.x, t = threadIdx.x;
    int lane = t & 31, w = t >> 5;
    int base = b * 1024 + t * 4;
    int x = 0;
#pragma unroll
    for (int j = 0; j < 4; j++) {
        int i = base + j;
        if (i < M_TOT) x += d_deg[i];
    }
    x = warp_isum(x);
    __shared__ int ws[8];
    if (lane == 0) ws[w] = x;
    __syncthreads();
    if (t == 0) {
        int tot = 0;
#pragma unroll
        for (int j = 0; j < 8; j++) tot += ws[j];
        d_bsum[b] = tot;
    }
}

// ---------------- kernel 4b: scan the 147 block sums ----------------
__global__ __launch_bounds__(256) void scan_p2() {
    int t = threadIdx.x, lane = t & 31, w = t >> 5;
    int v = (t < NB) ? d_bsum[t] : 0;
    int x = warp_iscan(v, lane);
    __shared__ int ws[8];
    if (lane == 31) ws[w] = x;
    __syncthreads();
    if (w == 0) {
        int y = (lane < 8) ? ws[lane] : 0;
        y = warp_iscan(y, lane);
        if (lane < 8) ws[lane] = y;
    }
    __syncthreads();
    int blk = (w > 0) ? ws[w - 1] : 0;
    if (t < NB) d_bsum[t] = x - v + blk;   // exclusive
}

// ---------------- kernel 4c: final scan + write offsets ----------------
__global__ __launch_bounds__(256) void scan_p3() {
    int b = blockIdx.x, t = threadIdx.x;
    int lane = t & 31, w = t >> 5;
    int base = b * 1024 + t * 4;
    int a[4];
#pragma unroll
    for (int j = 0; j < 4; j++) {
        int i = base + j;
        a[j] = (i < M_TOT) ? d_deg[i] : 0;
    }
    int tot = a[0] + a[1] + a[2] + a[3];
    int x = warp_iscan(tot, lane);
    __shared__ int ws[8];
    if (lane == 31) ws[w] = x;
    __syncthreads();
    if (w == 0) {
        int y = (lane < 8) ? ws[lane] : 0;
        y = warp_iscan(y, lane);
        if (lane < 8) ws[lane] = y;
    }
    __syncthreads();
    int blk = (w > 0) ? ws[w - 1] : 0;
    int excl = x - tot + blk + d_bsum[b];
    int run = excl;
#pragma unroll
    for (int j = 0; j < 4; j++) {
        int i = base + j;
        if (i < M_TOT) { d_off[i] = run; d_cur[i] = run; }
        run += a[j];
    }
    if (b == 0 && t == 0) d_off[M_TOT] = 3 * EE;
}

// ---------------- kernel 5: scatter into CSR ----------------
__global__ void scatter_kernel(const int* __restrict__ src0, const int* __restrict__ dst0,
                               const int* __restrict__ src1, const int* __restrict__ dst1,
                               const int* __restrict__ src2, const int* __restrict__ dst2) {
    int e = blockIdx.x * blockDim.x + threadIdx.x;
    int r = blockIdx.y;
    if (e >= EE) return;
    const int* src = (r == 0) ? src0 : (r == 1) ? src1 : src2;
    const int* dst = (r == 0) ? dst0 : (r == 1) ? dst1 : dst2;
    int dv = dst[e];
    int pos = atomicAdd(&d_cur[r * NN + dv], 1);
    d_ss[pos] = src[e];
}

// ---------------- kernel 6: gather + mean + relu + LN (warp per node) ----
__global__ __launch_bounds__(256) void agg_ln_kernel(const float* __restrict__ gamma,
                                                     const float* __restrict__ beta,
                                                     float* __restrict__ out) {
    int v = (blockIdx.x * blockDim.x + threadIdx.x) >> 5;
    if (v >= NN) return;
    int lane = threadIdx.x & 31;

    float acc[8];
#pragma unroll
    for (int j = 0; j < 8; j++) acc[j] = 0.0f;

#pragma unroll
    for (int r = 0; r < 3; r++) {
        int s = d_off[r * NN + v];
        int e = d_off[r * NN + v + 1];
        float sm[8];
#pragma unroll
        for (int j = 0; j < 8; j++) sm[j] = 0.0f;
        for (int i = s; i < e; i++) {
            int u = d_ss[i];
            const uint2* row = reinterpret_cast<const uint2*>(&d_h[(size_t)u * DD]);
            uint2 p = row[lane];
            uint2 q = row[lane + 32];
            float2 f0 = __half22float2(*reinterpret_cast<__half2*>(&p.x));
            float2 f1 = __half22float2(*reinterpret_cast<__half2*>(&p.y));
            float2 f2 = __half22float2(*reinterpret_cast<__half2*>(&q.x));
            float2 f3 = __half22float2(*reinterpret_cast<__half2*>(&q.y));
            sm[0] += f0.x; sm[1] += f0.y; sm[2] += f1.x; sm[3] += f1.y;
            sm[4] += f2.x; sm[5] += f2.y; sm[6] += f3.x; sm[7] += f3.y;
        }
        float inv = 1.0f / (float)max(e - s, 1);
#pragma unroll
        for (int j = 0; j < 8; j++) acc[j] += sm[j] * inv;
    }

#pragma unroll
    for (int j = 0; j < 8; j++) acc[j] = fmaxf(acc[j] * (1.0f / 3.0f), 0.0f);

    float loc = 0.0f;
#pragma unroll
    for (int j = 0; j < 8; j++) loc += acc[j];
    float mu = warp_sum(loc) * (1.0f / 256.0f);

    float vs = 0.0f;
#pragma unroll
    for (int j = 0; j < 8; j++) {
        float dlt = acc[j] - mu;
        vs += dlt * dlt;
    }
    float var = warp_sum(vs) * (1.0f / 256.0f);
    float rstd = rsqrtf(var + LN_EPS);

    const float4* g4 = reinterpret_cast<const float4*>(gamma);
    const float4* b4 = reinterpret_cast<const float4*>(beta);
    float4 ga = g4[lane], gb = g4[lane + 32];
    float4 ba = b4[lane], bb = b4[lane + 32];

    float4 o0, o1;
    o0.x = (acc[0] - mu) * rstd * ga.x + ba.x;
    o0.y = (acc[1] - mu) * rstd * ga.y + ba.y;
    o0.z = (acc[2] - mu) * rstd * ga.z + ba.z;
    o0.w = (acc[3] - mu) * rstd * ga.w + ba.w;
    o1.x = (acc[4] - mu) * rstd * gb.x + bb.x;
    o1.y = (acc[5] - mu) * rstd * gb.y + bb.y;
    o1.z = (acc[6] - mu) * rstd * gb.z + bb.z;
    o1.w = (acc[7] - mu) * rstd * gb.w + bb.w;

    float4* out4 = reinterpret_cast<float4*>(&out[(size_t)v * DD]);
    out4[lane] = o0;
    out4[lane + 32] = o1;
}

// ---------------- launch ----------------
extern "C" void kernel_launch(void* const* d_in, const int* in_sizes, int n_in,
                              void* d_out, int out_size) {
    const float* feat  = (const float*)d_in[0];
    const float* W0    = (const float*)d_in[1];
    const float* W1    = (const float*)d_in[2];
    const float* W2    = (const float*)d_in[3];
    const float* gamma = (const float*)d_in[7];
    const float* beta  = (const float*)d_in[8];
    const int* src0 = (const int*)d_in[9];
    const int* dst0 = (const int*)d_in[10];
    const int* src1 = (const int*)d_in[11];
    const int* dst1 = (const int*)d_in[12];
    const int* src2 = (const int*)d_in[13];
    const int* dst2 = (const int*)d_in[14];
    float* out = (float*)d_out;

    // Lazily-created side stream + fork/join events (resource init only; the
    // launched work is identical on every call and fully graph-capturable).
    static cudaStream_t s_side = nullptr;
    static cudaEvent_t ev_fork = nullptr, ev_join = nullptr;
    if (s_side == nullptr) {
        cudaStreamCreateWithFlags(&s_side, cudaStreamNonBlocking);
        cudaEventCreateWithFlags(&ev_fork, cudaEventDisableTiming);
        cudaEventCreateWithFlags(&ev_join, cudaEventDisableTiming);
    }

    prep_kernel<<<256, 256>>>(W0, W1, W2);

    // fork: CSR build on side stream, GEMM on main stream
    cudaEventRecord(ev_fork, 0);
    cudaStreamWaitEvent(s_side, ev_fork, 0);

    dim3 egrid((EE + 255) / 256, 3);
    hist_kernel<<<egrid, 256, 0, s_side>>>(dst0, dst1, dst2);
    scan_p1<<<NB, 256, 0, s_side>>>();
    scan_p2<<<1, 256, 0, s_side>>>();
    scan_p3<<<NB, 256, 0, s_side>>>();
    scatter_kernel<<<egrid, 256, 0, s_side>>>(src0, dst0, src1, dst1, src2, dst2);
    cudaEventRecord(ev_join, s_side);

    dim3 ggrid((NN + 127) / 128, DD / 64);
    gemm_kernel<<<ggrid, 256>>>(feat);

    // join
    cudaStreamWaitEvent(0, ev_join, 0);
    agg_ln_kernel<<<(NN * 32 + 255) / 256, 256>>>(gamma, beta, out);
}

// round 5
// speedup vs baseline: 1.4606x; 1.0101x over previous
#include <cuda_runtime.h>
#include <cuda_fp16.h>
#include <cstdint>

#define NN 50000
#define DD 256
#define EE 400000
#define LN_EPS 1e-5f

#define M_TOT (3 * NN)
#define NB ((M_TOT + 1023) / 1024)

// GEMM config
#define BM 128
#define BN 64
#define BK 64
#define STAGES 3
#define KTILES (DD / BK)          // 4
#define SA 36                      // uint32 row stride in smem (conflict-free)
#define A_STG (BM * SA)            // uint32s per A stage
#define B_STG (BN * SA)
#define GEMM_SMEM_BYTES ((STAGES * (A_STG + B_STG)) * 4)   // 82944

// ---------------- device scratch ----------------
__device__ __half d_Wh[DD * DD];              // ((W0+W1+W2)/3)^T fp16, [n][k]
__device__ __half d_feat16[(size_t)NN * DD];  // feat in fp16
__device__ __half d_h[(size_t)NN * DD];       // feat @ Wsum (fp16)
__device__ int    d_deg[M_TOT];
__device__ int    d_off[M_TOT + 1];
__device__ int    d_cur[M_TOT];
__device__ int    d_ss[3 * EE];
__device__ int    d_bsum[NB];

// ---------------- helpers ----------------
__device__ __forceinline__ void mma_f16(float (&d)[4], const uint32_t (&a)[4],
                                        const uint32_t (&b)[2]) {
    asm volatile(
        "mma.sync.aligned.m16n8k16.row.col.f32.f16.f16.f32 "
        "{%0,%1,%2,%3}, {%4,%5,%6,%7}, {%8,%9}, {%0,%1,%2,%3};\n"
        : "+f"(d[0]), "+f"(d[1]), "+f"(d[2]), "+f"(d[3])
        : "r"(a[0]), "r"(a[1]), "r"(a[2]), "r"(a[3]), "r"(b[0]), "r"(b[1]));
}

__device__ __forceinline__ void cp_async16(uint32_t dst_smem, const void* src, int src_bytes) {
    asm volatile("cp.async.cg.shared.global [%0], [%1], 16, %2;\n"
                 :: "r"(dst_smem), "l"(src), "r"(src_bytes));
}
__device__ __forceinline__ void cp_commit() { asm volatile("cp.async.commit_group;\n"); }
template <int N>
__device__ __forceinline__ void cp_wait() { asm volatile("cp.async.wait_group %0;\n" :: "n"(N)); }

__device__ __forceinline__ float warp_sum(float v) {
#pragma unroll
    for (int o = 16; o; o >>= 1) v += __shfl_xor_sync(0xFFFFFFFFu, v, o);
    return v;
}
__device__ __forceinline__ int warp_isum(int v) {
#pragma unroll
    for (int o = 16; o; o >>= 1) v += __shfl_xor_sync(0xFFFFFFFFu, v, o);
    return v;
}
__device__ __forceinline__ int warp_iscan(int x, int lane) {
#pragma unroll
    for (int ofs = 1; ofs < 32; ofs <<= 1) {
        int y = __shfl_up_sync(0xFFFFFFFFu, x, ofs);
        if (lane >= ofs) x += y;
    }
    return x;
}

// ---------------- prep: Wsum^T fp16 (main stream) ----------------
__global__ void prep_w_kernel(const float* __restrict__ W0, const float* __restrict__ W1,
                              const float* __restrict__ W2) {
    int stride = gridDim.x * blockDim.x;
    for (int i = blockIdx.x * blockDim.x + threadIdx.x; i < DD * DD; i += stride) {
        int n = i >> 8, k = i & 255;
        int src = k * DD + n;
        d_Wh[i] = __float2half_rn((W0[src] + W1[src] + W2[src]) * (1.0f / 3.0f));
    }
}

// ---------------- prep: zero deg (side stream) ----------------
__global__ void prep_deg_kernel() {
    int i = blockIdx.x * blockDim.x + threadIdx.x;
    if (i < M_TOT) d_deg[i] = 0;
}

// ---------------- convert feat -> fp16 ----------------
__global__ void convert_kernel(const float* __restrict__ feat) {
    int stride = gridDim.x * blockDim.x;
    const int total = NN * DD / 8;
    const float4* in = reinterpret_cast<const float4*>(feat);
    uint4* out = reinterpret_cast<uint4*>(d_feat16);
    for (int i = blockIdx.x * blockDim.x + threadIdx.x; i < total; i += stride) {
        float4 a = in[2 * i];
        float4 b = in[2 * i + 1];
        __half2 h0 = __floats2half2_rn(a.x, a.y);
        __half2 h1 = __floats2half2_rn(a.z, a.w);
        __half2 h2 = __floats2half2_rn(b.x, b.y);
        __half2 h3 = __floats2half2_rn(b.z, b.w);
        uint4 u;
        u.x = *reinterpret_cast<uint32_t*>(&h0);
        u.y = *reinterpret_cast<uint32_t*>(&h1);
        u.z = *reinterpret_cast<uint32_t*>(&h2);
        u.w = *reinterpret_cast<uint32_t*>(&h3);
        out[i] = u;
    }
}

// ---------------- GEMM: h = feat16 @ Wh^T, 3-stage cp.async pipeline ------
__global__ __launch_bounds__(256) void gemm_kernel() {
    extern __shared__ uint32_t smp[];
    uint32_t* As = smp;                      // [STAGES][BM*SA]
    uint32_t* Bs = smp + STAGES * A_STG;     // [STAGES][BN*SA]

    const int t    = threadIdx.x;
    const int lane = t & 31, wid = t >> 5;
    const int g    = lane >> 2, tig = lane & 3;
    const int wm   = wid & 3, wn = wid >> 2;

    const int rowBase = blockIdx.x * BM;
    const int colBase = blockIdx.y * BN;

    float acc[2][4][4];
#pragma unroll
    for (int mf = 0; mf < 2; mf++)
#pragma unroll
        for (int nf = 0; nf < 4; nf++)
#pragma unroll
            for (int k = 0; k < 4; k++) acc[mf][nf][k] = 0.0f;

    // A loader: 2 threads/row, 4x 16B chunks each (row has 8 chunks of 8 halves)
    const int aRow = t >> 1, aHalf = t & 1;
    const int aGr  = rowBase + aRow;
    const int aValid = (aGr < NN) ? 16 : 0;
    const __half* aSrc = &d_feat16[(size_t)(aGr < NN ? aGr : NN - 1) * DD];
    // B loader: 4 threads/row, 2x 16B chunks each
    const int bRow = t >> 2, bQ = t & 3;
    const __half* bSrc = &d_Wh[(colBase + bRow) * DD];

    const uint32_t asBase = (uint32_t)__cvta_generic_to_shared(As);
    const uint32_t bsBase = (uint32_t)__cvta_generic_to_shared(Bs);

    auto issue = [&](int stage, int kt) {
#pragma unroll
        for (int j = 0; j < 4; j++) {
            int chunk = aHalf * 4 + j;
            uint32_t dst = asBase + (stage * A_STG + aRow * SA + chunk * 4) * 4;
            cp_async16(dst, aSrc + kt + chunk * 8, aValid);
        }
#pragma unroll
        for (int j = 0; j < 2; j++) {
            int chunk = bQ * 2 + j;
            uint32_t dst = bsBase + (stage * B_STG + bRow * SA + chunk * 4) * 4;
            cp_async16(dst, bSrc + kt + chunk * 8, 16);
        }
    };

    issue(0, 0);
    cp_commit();
    issue(1, BK);
    cp_commit();

#pragma unroll
    for (int i = 0; i < KTILES; i++) {
        cp_wait<STAGES - 2>();
        __syncthreads();

        if (i + 2 < KTILES) issue((i + 2) % STAGES, (i + 2) * BK);
        cp_commit();

        const uint32_t* Ast = As + (i % STAGES) * A_STG;
        const uint32_t* Bst = Bs + (i % STAGES) * B_STG;

#pragma unroll
        for (int kk = 0; kk < 4; kk++) {
            uint32_t af[2][4], bf[4][2];
#pragma unroll
            for (int mf = 0; mf < 2; mf++) {
                int m0 = wm * 32 + mf * 16 + g;
                af[mf][0] = Ast[(m0)     * SA + kk * 8 + tig];
                af[mf][1] = Ast[(m0 + 8) * SA + kk * 8 + tig];
                af[mf][2] = Ast[(m0)     * SA + kk * 8 + tig + 4];
                af[mf][3] = Ast[(m0 + 8) * SA + kk * 8 + tig + 4];
            }
#pragma unroll
            for (int nf = 0; nf < 4; nf++) {
                int n0 = wn * 32 + nf * 8 + g;
                bf[nf][0] = Bst[n0 * SA + kk * 8 + tig];
                bf[nf][1] = Bst[n0 * SA + kk * 8 + tig + 4];
            }
#pragma unroll
            for (int mf = 0; mf < 2; mf++)
#pragma unroll
                for (int nf = 0; nf < 4; nf++) mma_f16(acc[mf][nf], af[mf], bf[nf]);
        }
        __syncthreads();
    }

    // epilogue -> fp16
#pragma unroll
    for (int mf = 0; mf < 2; mf++)
#pragma unroll
        for (int nf = 0; nf < 4; nf++) {
            int r0 = rowBase + wm * 32 + mf * 16 + g;
            int c  = colBase + wn * 32 + nf * 8 + tig * 2;
            if (r0 < NN)
                *reinterpret_cast<__half2*>(&d_h[(size_t)r0 * DD + c]) =
                    __floats2half2_rn(acc[mf][nf][0], acc[mf][nf][1]);
            int r1 = r0 + 8;
            if (r1 < NN)
                *reinterpret_cast<__half2*>(&d_h[(size_t)r1 * DD + c]) =
                    __floats2half2_rn(acc[mf][nf][2], acc[mf][nf][3]);
        }
}

// ---------------- degree histogram ----------------
__global__ void hist_kernel(const int* __restrict__ dst0, const int* __restrict__ dst1,
                            const int* __restrict__ dst2) {
    int e = blockIdx.x * blockDim.x + threadIdx.x;
    int r = blockIdx.y;
    if (e >= EE) return;
    const int* dst = (r == 0) ? dst0 : (r == 1) ? dst1 : dst2;
    atomicAdd(&d_deg[r * NN + dst[e]], 1);
}

// ---------------- scan p1/p2/p3 ----------------
__global__ __launch_bounds__(256) void scan_p1() {
    int b = blockIdx.x, t = threadIdx.x;
    int lane = t & 31, w = t >> 5;
    int base = b * 1024 + t * 4;
    int x = 0;
#pragma unroll
    for (int j = 0; j < 4; j++) {
        int i = base + j;
        if (i < M_TOT) x += d_deg[i];
    }
    x = warp_isum(x);
    __shared__ int ws[8];
    if (lane == 0) ws[w] = x;
    __syncthreads();
    if (t == 0) {
        int tot = 0;
#pragma unroll
        for (int j = 0; j < 8; j++) tot += ws[j];
        d_bsum[b] = tot;
    }
}

__global__ __launch_bounds__(256) void scan_p2() {
    int t = threadIdx.x, lane = t & 31, w = t >> 5;
    int v = (t < NB) ? d_bsum[t] : 0;
    int x = warp_iscan(v, lane);
    __shared__ int ws[8];
    if (lane == 31) ws[w] = x;
    __syncthreads();
    if (w == 0) {
        int y = (lane < 8) ? ws[lane] : 0;
        y = warp_iscan(y, lane);
        if (lane < 8) ws[lane] = y;
    }
    __syncthreads();
    int blk = (w > 0) ? ws[w - 1] : 0;
    if (t < NB) d_bsum[t] = x - v + blk;
}

__global__ __launch_bounds__(256) void scan_p3() {
    int b = blockIdx.x, t = threadIdx.x;
    int lane = t & 31, w = t >> 5;
    int base = b * 1024 + t * 4;
    int a[4];
#pragma unroll
    for (int j = 0; j < 4; j++) {
        int i = base + j;
        a[j] = (i < M_TOT) ? d_deg[i] : 0;
    }
    int tot = a[0] + a[1] + a[2] + a[3];
    int x = warp_iscan(tot, lane);
    __shared__ int ws[8];
    if (lane == 31) ws[w] = x;
    __syncthreads();
    if (w == 0) {
        int y = (lane < 8) ? ws[lane] : 0;
        y = warp_iscan(y, lane);
        if (lane < 8) ws[lane] = y;
    }
    __syncthreads();
    int blk = (w > 0) ? ws[w - 1] : 0;
    int excl = x - tot + blk + d_bsum[b];
    int run = excl;
#pragma unroll
    for (int j = 0; j < 4; j++) {
        int i = base + j;
        if (i < M_TOT) { d_off[i] = run; d_cur[i] = run; }
        run += a[j];
    }
    if (b == 0 && t == 0) d_off[M_TOT] = 3 * EE;
}

// ---------------- scatter into CSR ----------------
__global__ void scatter_kernel(const int* __restrict__ src0, const int* __restrict__ dst0,
                               const int* __restrict__ src1, const int* __restrict__ dst1,
                               const int* __restrict__ src2, const int* __restrict__ dst2) {
    int e = blockIdx.x * blockDim.x + threadIdx.x;
    int r = blockIdx.y;
    if (e >= EE) return;
    const int* src = (r == 0) ? src0 : (r == 1) ? src1 : src2;
    const int* dst = (r == 0) ? dst0 : (r == 1) ? dst1 : dst2;
    int dv = dst[e];
    int pos = atomicAdd(&d_cur[r * NN + dv], 1);
    d_ss[pos] = src[e];
}

// ---------------- gather + mean + relu + LN (warp per node) ----------------
__global__ __launch_bounds__(256) void agg_ln_kernel(const float* __restrict__ gamma,
                                                     const float* __restrict__ beta,
                                                     float* __restrict__ out) {
    int v = (blockIdx.x * blockDim.x + threadIdx.x) >> 5;
    if (v >= NN) return;
    int lane = threadIdx.x & 31;

    float acc[8];
#pragma unroll
    for (int j = 0; j < 8; j++) acc[j] = 0.0f;

#pragma unroll
    for (int r = 0; r < 3; r++) {
        int s = d_off[r * NN + v];
        int e = d_off[r * NN + v + 1];
        float sm[8];
#pragma unroll
        for (int j = 0; j < 8; j++) sm[j] = 0.0f;
        for (int i = s; i < e; i++) {
            int u = d_ss[i];
            const uint2* row = reinterpret_cast<const uint2*>(&d_h[(size_t)u * DD]);
            uint2 p = row[lane];
            uint2 q = row[lane + 32];
            float2 f0 = __half22float2(*reinterpret_cast<__half2*>(&p.x));
            float2 f1 = __half22float2(*reinterpret_cast<__half2*>(&p.y));
            float2 f2 = __half22float2(*reinterpret_cast<__half2*>(&q.x));
            float2 f3 = __half22float2(*reinterpret_cast<__half2*>(&q.y));
            sm[0] += f0.x; sm[1] += f0.y; sm[2] += f1.x; sm[3] += f1.y;
            sm[4] += f2.x; sm[5] += f2.y; sm[6] += f3.x; sm[7] += f3.y;
        }
        float inv = 1.0f / (float)max(e - s, 1);
#pragma unroll
        for (int j = 0; j < 8; j++) acc[j] += sm[j] * inv;
    }

#pragma unroll
    for (int j = 0; j < 8; j++) acc[j] = fmaxf(acc[j] * (1.0f / 3.0f), 0.0f);

    float loc = 0.0f;
#pragma unroll
    for (int j = 0; j < 8; j++) loc += acc[j];
    float mu = warp_sum(loc) * (1.0f / 256.0f);

    float vs = 0.0f;
#pragma unroll
    for (int j = 0; j < 8; j++) {
        float dlt = acc[j] - mu;
        vs += dlt * dlt;
    }
    float var = warp_sum(vs) * (1.0f / 256.0f);
    float rstd = rsqrtf(var + LN_EPS);

    const float4* g4 = reinterpret_cast<const float4*>(gamma);
    const float4* b4 = reinterpret_cast<const float4*>(beta);
    float4 ga = g4[lane], gb = g4[lane + 32];
    float4 ba = b4[lane], bb = b4[lane + 32];

    float4 o0, o1;
    o0.x = (acc[0] - mu) * rstd * ga.x + ba.x;
    o0.y = (acc[1] - mu) * rstd * ga.y + ba.y;
    o0.z = (acc[2] - mu) * rstd * ga.z + ba.z;
    o0.w = (acc[3] - mu) * rstd * ga.w + ba.w;
    o1.x = (acc[4] - mu) * rstd * gb.x + bb.x;
    o1.y = (acc[5] - mu) * rstd * gb.y + bb.y;
    o1.z = (acc[6] - mu) * rstd * gb.z + bb.z;
    o1.w = (acc[7] - mu) * rstd * gb.w + bb.w;

    float4* out4 = reinterpret_cast<float4*>(&out[(size_t)v * DD]);
    out4[lane] = o0;
    out4[lane + 32] = o1;
}

// ---------------- launch ----------------
extern "C" void kernel_launch(void* const* d_in, const int* in_sizes, int n_in,
                              void* d_out, int out_size) {
    const float* feat  = (const float*)d_in[0];
    const float* W0    = (const float*)d_in[1];
    const float* W1    = (const float*)d_in[2];
    const float* W2    = (const float*)d_in[3];
    const float* gamma = (const float*)d_in[7];
    const float* beta  = (const float*)d_in[8];
    const int* src0 = (const int*)d_in[9];
    const int* dst0 = (const int*)d_in[10];
    const int* src1 = (const int*)d_in[11];
    const int* dst1 = (const int*)d_in[12];
    const int* src2 = (const int*)d_in[13];
    const int* dst2 = (const int*)d_in[14];
    float* out = (float*)d_out;

    static cudaStream_t s_side = nullptr;
    static cudaEvent_t ev_fork = nullptr, ev_join = nullptr;
    if (s_side == nullptr) {
        cudaStreamCreateWithFlags(&s_side, cudaStreamNonBlocking);
        cudaEventCreateWithFlags(&ev_fork, cudaEventDisableTiming);
        cudaEventCreateWithFlags(&ev_join, cudaEventDisableTiming);
        cudaFuncSetAttribute(gemm_kernel, cudaFuncAttributeMaxDynamicSharedMemorySize,
                             GEMM_SMEM_BYTES);
    }

    // fork immediately: CSR build chain is independent of the GEMM chain
    cudaEventRecord(ev_fork, 0);
    cudaStreamWaitEvent(s_side, ev_fork, 0);

    // side stream: zero deg -> hist -> scan -> scatter
    prep_deg_kernel<<<(M_TOT + 255) / 256, 256, 0, s_side>>>();
    dim3 egrid((EE + 255) / 256, 3);
    hist_kernel<<<egrid, 256, 0, s_side>>>(dst0, dst1, dst2);
    scan_p1<<<NB, 256, 0, s_side>>>();
    scan_p2<<<1, 256, 0, s_side>>>();
    scan_p3<<<NB, 256, 0, s_side>>>();
    scatter_kernel<<<egrid, 256, 0, s_side>>>(src0, dst0, src1, dst1, src2, dst2);
    cudaEventRecord(ev_join, s_side);

    // main stream: Wsum -> feat fp16 -> GEMM
    prep_w_kernel<<<64, 256>>>(W0, W1, W2);
    convert_kernel<<<592, 256>>>(feat);
    dim3 ggrid((NN + BM - 1) / BM, DD / BN);
    gemm_kernel<<<ggrid, 256, GEMM_SMEM_BYTES>>>();

    // join
    cudaStreamWaitEvent(0, ev_join, 0);
    agg_ln_kernel<<<(NN * 32 + 255) / 256, 256>>>(gamma, beta, out);
}